// round 12
// baseline (speedup 1.0000x reference)
#include <cuda_runtime.h>
#include <string.h>
#include <stdint.h>

#define EPS 1e-5f

// ---------------- folded-weight scratch (device globals: allowed) ----------
__device__ __align__(16) float g_W1t[512 * 192];     // [c][j], BN1 scale folded
__device__ __align__(16) float g_b1f[192];           // BN1 folded bias
__device__ __align__(16) float g_W4t[64 * 512];      // [d][c], BN2 scale folded
__device__ __align__(16) float g_c4f[512];           // BN2 folded bias

// ---------------- prep: fold BN into weights -------------------------------
__global__ void prep_kernel(const float* __restrict__ W123, const float* __restrict__ b123,
                            const float* __restrict__ g123, const float* __restrict__ be123,
                            const float* __restrict__ m123, const float* __restrict__ v123,
                            const float* __restrict__ W4,   const float* __restrict__ b4,
                            const float* __restrict__ g4,   const float* __restrict__ be4,
                            const float* __restrict__ m4,   const float* __restrict__ v4)
{
    int idx = blockIdx.x * blockDim.x + threadIdx.x;
    if (idx < 512 * 192) {
        int c = idx / 192, j = idx % 192;
        float s = g123[j] * rsqrtf(v123[j] + EPS);
        g_W1t[c * 192 + j] = W123[j * 512 + c] * s;
    }
    int i2 = idx - 512 * 192;
    if (i2 >= 0 && i2 < 192) {
        float s = g123[i2] * rsqrtf(v123[i2] + EPS);
        g_b1f[i2] = (b123[i2] - m123[i2]) * s + be123[i2];
    }
    int i3 = idx - (512 * 192 + 192);
    if (i3 >= 0 && i3 < 64 * 512) {
        int d = i3 / 512, c = i3 % 512;
        float s = g4[c] * rsqrtf(v4[c] + EPS);
        g_W4t[i3] = W4[c * 64 + d] * s;
    }
    int i4 = idx - (512 * 192 + 192 + 64 * 512);
    if (i4 >= 0 && i4 < 512) {
        float s = g4[i4] * rsqrtf(v4[i4] + EPS);
        g_c4f[i4] = (b4[i4] - m4[i4]) * s + be4[i4];
    }
}

// ---------------- helpers ---------------------------------------------------
__device__ __forceinline__ float2 ffma2(float2 a, float2 b, float2 c) {
    unsigned long long au, bu, cu, du;
    memcpy(&au, &a, 8); memcpy(&bu, &b, 8); memcpy(&cu, &c, 8);
    asm("fma.rn.f32x2 %0, %1, %2, %3;" : "=l"(du) : "l"(au), "l"(bu), "l"(cu));
    float2 d; memcpy(&d, &du, 8); return d;
}

// SMEM (floats):
//   [0, 34816)        A_T[512][68]  (k-major xs, 16 samples x 4 rows)
//   [34816, 51328)    act[64][192] (12288), then yS 2 x 8256 (16512)
//   [51328, 55488)    sATT 16 x 260
#define SMF 55488

__global__ void __launch_bounds__(768, 1)
fused_kernel(const float* __restrict__ x, float* __restrict__ out)
{
    extern __shared__ float sm[];
    float* sAT  = sm;
    float* sMID = sm + 34816;          // act, then yS
    float* sATT = sm + 51328;

    const int t    = threadIdx.x;
    const int warp = t >> 5;           // 24 warps
    const int lane = t & 31;
    const int rh   = warp & 1;
    const int cg1  = warp >> 1;        // GEMM1 col-group 0..11
    const int n0   = blockIdx.x * 16;

    const float4* xb = (const float4*)x;

    // ---- Phase 0: gather xs into A_T[c][row], row=4*i+l (8-wf LDG pattern)
    {
        const int cl = lane >> 1;            // c within 16-block
        const int hs = lane & 1;             // h selector: 0 -> h=0, 1 -> h=2
        for (int u = warp; u < 512; u += 24) {
            int i  = u >> 5, cb = u & 31;
            int c  = cb * 16 + cl;
            long f4 = ((long)(n0 + i) * 512 + c) * 4 + hs * 2;
            float4 v = __ldg(&xb[f4]);
            *(float2*)&sAT[c * 68 + 4 * i + 2 * hs] = make_float2(v.x, v.z);
        }
    }
    __syncthreads();

    // ---- Phase 1: GEMM1 [64r][192c]; warp 32r x 16c; BARRIER-FREE.
    //      a from smem (LDS.128 conflict-free), b streamed from L1 via LDG.
    float2 acc[4][2];
    #pragma unroll
    for (int r = 0; r < 4; r++) {
        acc[r][0] = make_float2(0.f, 0.f);
        acc[r][1] = make_float2(0.f, 0.f);
    }
    const int r0 = rh * 32 + (lane >> 2) * 4;
    const int j0 = cg1 * 16 + (lane & 3) * 4;

    #define FMA8(av, bv)                                                        \
        do {                                                                    \
            float2 b01 = make_float2((bv).x, (bv).y);                           \
            float2 b23 = make_float2((bv).z, (bv).w);                           \
            acc[0][0] = ffma2(make_float2((av).x, (av).x), b01, acc[0][0]);     \
            acc[0][1] = ffma2(make_float2((av).x, (av).x), b23, acc[0][1]);     \
            acc[1][0] = ffma2(make_float2((av).y, (av).y), b01, acc[1][0]);     \
            acc[1][1] = ffma2(make_float2((av).y, (av).y), b23, acc[1][1]);     \
            acc[2][0] = ffma2(make_float2((av).z, (av).z), b01, acc[2][0]);     \
            acc[2][1] = ffma2(make_float2((av).z, (av).z), b23, acc[2][1]);     \
            acc[3][0] = ffma2(make_float2((av).w, (av).w), b01, acc[3][0]);     \
            acc[3][1] = ffma2(make_float2((av).w, (av).w), b23, acc[3][1]);     \
        } while (0)

    {
        const float* abase = sAT + r0;
        const float* bgp   = g_W1t + j0;
        float4 a0 = *(const float4*)&abase[0];
        float4 b0 = __ldg((const float4*)bgp);
        #pragma unroll 8
        for (int kk = 0; kk < 511; kk++) {
            float4 a1 = *(const float4*)&abase[(kk + 1) * 68];
            float4 b1 = __ldg((const float4*)(bgp + (kk + 1) * 192));
            FMA8(a0, b0);
            a0 = a1; b0 = b1;
        }
        FMA8(a0, b0);
    }
    __syncthreads();   // A_T dead after this (sMID unrelated, but keep order)

    // ---- act = relu(acc + bias) -> act[64][192]
    float* act = sMID;
    {
        float4 bias = __ldg((const float4*)&g_b1f[j0]);
        #pragma unroll
        for (int r = 0; r < 4; r++) {
            float4 o;
            o.x = fmaxf(acc[r][0].x + bias.x, 0.f);
            o.y = fmaxf(acc[r][0].y + bias.y, 0.f);
            o.z = fmaxf(acc[r][1].x + bias.z, 0.f);
            o.w = fmaxf(acc[r][1].y + bias.w, 0.f);
            *(float4*)&act[(r0 + r) * 192 + j0] = o;
        }
    }
    __syncthreads();   // act complete

    // ---- Phase 2: warp-local 4x4 attention (warps 0..15, warp = sample)
    if (warp < 16) {
        const int s = warp, g = lane;
        float2 q2[4], k2[4], v2[4];
        #pragma unroll
        for (int l = 0; l < 4; l++) {
            const float* ar = act + (4 * s + l) * 192;
            q2[l] = *(const float2*)&ar[2 * g];
            k2[l] = *(const float2*)&ar[2 * g + 64];
            v2[l] = *(const float2*)&ar[2 * g + 128];
        }
        float sc[16];
        #pragma unroll
        for (int l = 0; l < 4; l++)
            #pragma unroll
            for (int m = 0; m < 4; m++)
                sc[l * 4 + m] = q2[l].x * k2[m].x + q2[l].y * k2[m].y;
        #pragma unroll
        for (int off = 16; off > 0; off >>= 1)
            #pragma unroll
            for (int i = 0; i < 16; i++)
                sc[i] += __shfl_xor_sync(0xffffffffu, sc[i], off);

        #pragma unroll
        for (int l = 0; l < 4; l++) {
            float s0 = sc[l*4+0], s1 = sc[l*4+1], s2 = sc[l*4+2], s3 = sc[l*4+3];
            float mx = fmaxf(fmaxf(s0, s1), fmaxf(s2, s3));
            float e0 = __expf(s0 - mx), e1 = __expf(s1 - mx);
            float e2 = __expf(s2 - mx), e3 = __expf(s3 - mx);
            float inv = 1.f / (e0 + e1 + e2 + e3);
            float ax = (e0*v2[0].x + e1*v2[1].x + e2*v2[2].x + e3*v2[3].x) * inv;
            float ay = (e0*v2[0].y + e1*v2[1].y + e2*v2[2].y + e3*v2[3].y) * inv;
            sATT[s * 260 + (2*g)   * 4 + l] = ax;
            sATT[s * 260 + (2*g+1) * 4 + l] = ay;
        }
    }
    __syncthreads();   // sATT complete; act dead -> yS region

    // ---- Phase 3 (R8 alternation): GEMM2 (w via LDG/L1) + coalesced epilogue
    float* yS = sMID;
    const int sI  = lane & 15;
    const int cgr = lane >> 4;

    auto compute_y = [&](int cc) {
        float* yb = yS + (cc & 1) * 8256;
        const int cb = cc * 128 + warp * 8 + cgr * 4;
        float2 y01[4], y23[4];
        #pragma unroll
        for (int cp = 0; cp < 4; cp++) {
            y01[cp] = make_float2(0.f, 0.f);
            y23[cp] = make_float2(0.f, 0.f);
        }
        const float* attn = sATT + sI * 260;
        const float* wgp  = g_W4t + cb;
        float4 av = *(const float4*)&attn[0];
        float4 wv = __ldg((const float4*)wgp);
        #pragma unroll 7
        for (int d = 0; d < 63; d++) {
            float4 avn = *(const float4*)&attn[(d + 1) * 4];
            float4 wvn = __ldg((const float4*)(wgp + (d + 1) * 512));
            float2 a01 = make_float2(av.x, av.y), a23 = make_float2(av.z, av.w);
            const float* wvp = &wv.x;
            #pragma unroll
            for (int cp = 0; cp < 4; cp++) {
                float2 wb = make_float2(wvp[cp], wvp[cp]);
                y01[cp] = ffma2(a01, wb, y01[cp]);
                y23[cp] = ffma2(a23, wb, y23[cp]);
            }
            av = avn; wv = wvn;
        }
        {
            float2 a01 = make_float2(av.x, av.y), a23 = make_float2(av.z, av.w);
            const float* wvp = &wv.x;
            #pragma unroll
            for (int cp = 0; cp < 4; cp++) {
                float2 wb = make_float2(wvp[cp], wvp[cp]);
                y01[cp] = ffma2(a01, wb, y01[cp]);
                y23[cp] = ffma2(a23, wb, y23[cp]);
            }
        }
        float4 cf = __ldg((const float4*)&g_c4f[cb]);
        const float* cfp = &cf.x;
        const int fb = (warp * 8 + cgr * 4) * 4;
        #pragma unroll
        for (int cp = 0; cp < 4; cp++) {
            *(float4*)&yb[sI * 516 + fb + cp * 4] =
                make_float4(y01[cp].x + cfp[cp], y01[cp].y + cfp[cp],
                            y23[cp].x + cfp[cp], y23[cp].y + cfp[cp]);
        }
    };
    auto epilogue = [&](int cc, int wfirst, int wcount) {
        const float* ys = yS + (cc & 1) * 8256;
        for (int u = warp - wfirst; u < 256; u += wcount) {
            const int s = u >> 4, i = u & 15;
            const int f = i * 32 + lane;
            float yv = ys[s * 516 + f];
            long b4i = ((long)(n0 + s) * 512 + cc * 128) * 4 + f;
            float4 v = __ldg(&xb[b4i]);
            v.x += yv; v.y += yv; v.z += yv; v.w += yv;
            ((float4*)out)[b4i] = v;
        }
    };

    if (warp < 16) compute_y(0);
    __syncthreads();
    #pragma unroll
    for (int cc = 1; cc < 4; cc++) {
        if (warp < 16) compute_y(cc);
        else           epilogue(cc - 1, 16, 8);
        __syncthreads();
    }
    epilogue(3, 0, 24);
}

extern "C" void kernel_launch(void* const* d_in, const int* in_sizes, int n_in,
                              void* d_out, int out_size)
{
    const float* x    = (const float*)d_in[0];
    const float* W123 = (const float*)d_in[1];
    const float* b123 = (const float*)d_in[2];
    const float* g123 = (const float*)d_in[3];
    const float* be123= (const float*)d_in[4];
    const float* m123 = (const float*)d_in[5];
    const float* v123 = (const float*)d_in[6];
    const float* W4   = (const float*)d_in[7];
    const float* b4   = (const float*)d_in[8];
    const float* g4   = (const float*)d_in[9];
    const float* be4  = (const float*)d_in[10];
    const float* m4   = (const float*)d_in[11];
    const float* v4   = (const float*)d_in[12];

    int N = in_sizes[0] / (512 * 16);   // 2048

    prep_kernel<<<515, 256>>>(W123, b123, g123, be123, m123, v123,
                              W4, b4, g4, be4, m4, v4);

    cudaFuncSetAttribute(fused_kernel, cudaFuncAttributeMaxDynamicSharedMemorySize,
                         SMF * 4);
    fused_kernel<<<N / 16, 768, SMF * 4>>>(x, (float*)d_out);
}

// round 13
// speedup vs baseline: 1.0802x; 1.0802x over previous
#include <cuda_runtime.h>
#include <string.h>
#include <stdint.h>

#define EPS 1e-5f

// ---------------- folded-weight scratch (device globals: allowed) ----------
__device__ __align__(16) float g_W1t[512 * 192];     // [c][j], BN1 scale folded
__device__ __align__(16) float g_b1f[192];           // BN1 folded bias
__device__ __align__(16) float g_W4t[64 * 512];      // [d][c], BN2 scale folded
__device__ __align__(16) float g_c4f[512];           // BN2 folded bias

// ---------------- prep: fold BN into weights (tiled transposes) ------------
__global__ void prep_kernel(const float* __restrict__ W123, const float* __restrict__ b123,
                            const float* __restrict__ g123, const float* __restrict__ be123,
                            const float* __restrict__ m123, const float* __restrict__ v123,
                            const float* __restrict__ W4,   const float* __restrict__ b4,
                            const float* __restrict__ g4,   const float* __restrict__ be4,
                            const float* __restrict__ m4,   const float* __restrict__ v4)
{
    __shared__ float tile[32][33];
    const int b  = blockIdx.x;
    const int tx = threadIdx.x & 31;
    const int ty = threadIdx.x >> 5;          // 0..7

    if (b < 96) {
        // W1t[c][j] = W123[j][c] * s1[j] ;  jt in [0,6), ct in [0,16)
        const int jt = b / 16, ct = b % 16;
        #pragma unroll
        for (int k = 0; k < 4; k++) {
            int jy = ty + k * 8;
            int j  = jt * 32 + jy, c = ct * 32 + tx;
            float s = g123[j] * rsqrtf(v123[j] + EPS);
            tile[jy][tx] = W123[j * 512 + c] * s;       // coalesced read
        }
        __syncthreads();
        #pragma unroll
        for (int k = 0; k < 4; k++) {
            int cy = ty + k * 8;
            int c  = ct * 32 + cy, j = jt * 32 + tx;
            g_W1t[c * 192 + j] = tile[tx][cy];          // coalesced write
        }
    } else if (b < 128) {
        // W4t[d][c] = W4[c][d] * s4[c] ;  dt in [0,2), ct in [0,16)
        const int bb = b - 96;
        const int dt = bb / 16, ct = bb % 16;
        #pragma unroll
        for (int k = 0; k < 4; k++) {
            int cy = ty + k * 8;
            int c  = ct * 32 + cy, d = dt * 32 + tx;
            float s = g4[c] * rsqrtf(v4[c] + EPS);
            tile[cy][tx] = W4[c * 64 + d] * s;          // coalesced read
        }
        __syncthreads();
        #pragma unroll
        for (int k = 0; k < 4; k++) {
            int dy = ty + k * 8;
            int d  = dt * 32 + dy, c = ct * 32 + tx;
            g_W4t[d * 512 + c] = tile[tx][dy];          // coalesced write
        }
    } else {
        // biases
        int i = threadIdx.x;
        if (i < 192) {
            float s = g123[i] * rsqrtf(v123[i] + EPS);
            g_b1f[i] = (b123[i] - m123[i]) * s + be123[i];
        }
        for (int c = i; c < 512; c += 256) {
            float s = g4[c] * rsqrtf(v4[c] + EPS);
            g_c4f[c] = (b4[c] - m4[c]) * s + be4[c];
        }
    }
}

// ---------------- helpers ---------------------------------------------------
__device__ __forceinline__ float2 ffma2(float2 a, float2 b, float2 c) {
    unsigned long long au, bu, cu, du;
    memcpy(&au, &a, 8); memcpy(&bu, &b, 8); memcpy(&cu, &c, 8);
    asm("fma.rn.f32x2 %0, %1, %2, %3;" : "=l"(du) : "l"(au), "l"(bu), "l"(cu));
    float2 d; memcpy(&d, &du, 8); return d;
}
__device__ __forceinline__ uint32_t smem_u32(const void* p) {
    uint32_t a;
    asm("{ .reg .u64 t; cvta.to.shared.u64 t, %1; cvt.u32.u64 %0, t; }" : "=r"(a) : "l"(p));
    return a;
}
__device__ __forceinline__ void mbar_init(uint32_t a, uint32_t cnt) {
    asm volatile("mbarrier.init.shared.b64 [%0], %1;" :: "r"(a), "r"(cnt) : "memory");
}
__device__ __forceinline__ void mbar_expect_tx(uint32_t a, uint32_t bytes) {
    asm volatile("mbarrier.arrive.expect_tx.shared.b64 _, [%0], %1;" :: "r"(a), "r"(bytes) : "memory");
}
__device__ __forceinline__ void mbar_wait(uint32_t a, uint32_t parity) {
    asm volatile(
        "{\n\t.reg .pred P;\n\t"
        "WL%=:\n\t"
        "mbarrier.try_wait.parity.acquire.cta.shared::cta.b64 P, [%0], %1, 0x989680;\n\t"
        "@P bra WD%=;\n\t"
        "bra.uni WL%=;\n\t"
        "WD%=:\n\t}"
        :: "r"(a), "r"(parity) : "memory");
}
__device__ __forceinline__ void bulk_g2s(uint32_t dst_smem, const float* gsrc,
                                         uint32_t bytes, uint32_t mbar) {
    asm volatile(
        "cp.async.bulk.shared::cluster.global.mbarrier::complete_tx::bytes [%0], [%1], %2, [%3];"
        :: "r"(dst_smem), "l"(gsrc), "r"(bytes), "r"(mbar) : "memory");
}
__device__ __forceinline__ void cp_async4(float* d, const float* s) {
    unsigned sd = (unsigned)__cvta_generic_to_shared(d);
    asm volatile("cp.async.ca.shared.global [%0], [%1], 4;" :: "r"(sd), "l"(s));
}
#define CP_COMMIT()  asm volatile("cp.async.commit_group;")
#define CP_WAIT(n)   asm volatile("cp.async.wait_group %0;" :: "n"(n))
#define FENCE_ASYNC() asm volatile("fence.proxy.async.shared::cta;" ::: "memory")

// SMEM (floats):
//   [0, 34816)        A_T[512][68]; reused after GEMM1: W4s[64][512]
//   [34816, 53248)    3 x 6144 GEMM1 weight stages; reused: act[64][192],
//                     then yS 2 x 8256
//   [53248, 57408)    sATT 16 x 260
//   [57408, 57416)    4 mbarriers
#define SMF 57416

__global__ void __launch_bounds__(768, 1)
fused_kernel(const float* __restrict__ x, float* __restrict__ out)
{
    extern __shared__ float sm[];
    float* sAT  = sm;                  // later: W4s
    float* sB   = sm + 34816;          // later: act, then yS buffers
    float* sATT = sm + 53248;
    const uint32_t smb  = smem_u32(sm);
    const uint32_t smbB = smb + 34816u * 4u;
    const uint32_t MBAR = smb + 57408u * 4u;   // +8*k, k=0..2 GEMM1, k=3 W4

    const int t    = threadIdx.x;
    const int warp = t >> 5;           // 24 warps
    const int lane = t & 31;
    const int rh   = warp & 1;
    const int cg1  = warp >> 1;        // GEMM1 col-group 0..11
    const int n0   = blockIdx.x * 16;

    const int cl = lane >> 1;          // gather: channel within 16-block
    const int hs = lane & 1;           // gather: h selector (0 -> h=0, 1 -> h=2)

    if (t == 0) {
        mbar_init(MBAR + 0,  1);
        mbar_init(MBAR + 8,  1);
        mbar_init(MBAR + 16, 1);
        mbar_init(MBAR + 24, 1);
    }
    __syncthreads();
    if (t == 0) {
        #pragma unroll
        for (int b = 0; b < 3; b++) {
            mbar_expect_tx(MBAR + 8u * b, 24576);
            bulk_g2s(smbB + 24576u * b, g_W1t + b * 6144, 24576, MBAR + 8u * b);
        }
    }

    const float4* xb = (const float4*)x;

    // ---- gather group issuer: chunk g covers channels [32g, 32g+32), all 16
    //      samples. 32 units (i, cb) over 24 warps; lane = (cl, hs); two 4B
    //      cp.asyncs per lane (w=0 and w=2 of row h). Commits EMPTY groups
    //      for g >= 16 to keep per-thread group counts uniform.
    auto issue_gather = [&](int g) {
        if (g < 16) {
            #pragma unroll
            for (int rep = 0; rep < 2; rep++) {
                int v = warp + rep * 24;
                if (v < 32) {
                    int i  = v >> 1, cb = v & 1;
                    int c  = g * 32 + cb * 16 + cl;
                    const float* src = x + ((long)((n0 + i) * 512 + c)) * 16 + hs * 8;
                    float* dst = &sAT[c * 68 + 4 * i + 2 * hs];
                    cp_async4(dst,     src);       // w = 0
                    cp_async4(dst + 1, src + 2);   // w = 2
                }
            }
        }
        CP_COMMIT();
    };

    // prologue: chunks 0..2 in flight
    issue_gather(0);
    issue_gather(1);
    issue_gather(2);
    CP_WAIT(2);        // chunk 0 done (own copies)
    __syncthreads();   // chunk 0 visible to all

    // ---- Phase 1: GEMM1 [64r][192c]; warp 32r x 16c; 3-deep weight TMA
    //      pipeline + 3-deep gather cp.async pipeline; software-pipelined LDS.
    float2 acc[4][2];
    #pragma unroll
    for (int r = 0; r < 4; r++) {
        acc[r][0] = make_float2(0.f, 0.f);
        acc[r][1] = make_float2(0.f, 0.f);
    }
    const int r0 = rh * 32 + (lane >> 2) * 4;
    const int j0 = cg1 * 16 + (lane & 3) * 4;

    #define FMA8(av, bv)                                                        \
        do {                                                                    \
            float2 b01 = make_float2((bv).x, (bv).y);                           \
            float2 b23 = make_float2((bv).z, (bv).w);                           \
            acc[0][0] = ffma2(make_float2((av).x, (av).x), b01, acc[0][0]);     \
            acc[0][1] = ffma2(make_float2((av).x, (av).x), b23, acc[0][1]);     \
            acc[1][0] = ffma2(make_float2((av).y, (av).y), b01, acc[1][0]);     \
            acc[1][1] = ffma2(make_float2((av).y, (av).y), b23, acc[1][1]);     \
            acc[2][0] = ffma2(make_float2((av).z, (av).z), b01, acc[2][0]);     \
            acc[2][1] = ffma2(make_float2((av).z, (av).z), b23, acc[2][1]);     \
            acc[3][0] = ffma2(make_float2((av).w, (av).w), b01, acc[3][0]);     \
            acc[3][1] = ffma2(make_float2((av).w, (av).w), b23, acc[3][1]);     \
        } while (0)

    int buf = 0;
    for (int st = 0; st < 16; st++) {
        mbar_wait(MBAR + 8u * buf, ((unsigned)st / 3u) & 1u);

        const float* bbase = sB + buf * 6144 + j0;
        const float* abase = sAT + (st * 32) * 68 + r0;

        float4 a0 = *(const float4*)&abase[0];
        float4 b0 = *(const float4*)&bbase[0];
        #pragma unroll 31
        for (int kk = 0; kk < 31; kk++) {
            float4 a1 = *(const float4*)&abase[(kk + 1) * 68];
            float4 b1 = *(const float4*)&bbase[(kk + 1) * 192];
            FMA8(a0, b0);
            a0 = a1; b0 = b1;
        }
        FMA8(a0, b0);

        CP_WAIT(1);        // own copies of gather chunk st+1 complete
        __syncthreads();   // weight buffer consumed + chunk st+1 visible

        if (st + 3 < 16 && t == 0) {
            mbar_expect_tx(MBAR + 8u * buf, 24576);
            bulk_g2s(smbB + 24576u * buf, g_W1t + (st + 3) * 6144, 24576,
                     MBAR + 8u * buf);
        }
        issue_gather(st + 3);
        buf = (buf == 2) ? 0 : buf + 1;
    }
    // sAT & sB dead. Kick off full W4 load into old sAT region.
    if (t == 0) {
        FENCE_ASYNC();
        mbar_expect_tx(MBAR + 24, 131072);
        bulk_g2s(smb, g_W4t, 131072, MBAR + 24);
    }

    // ---- act = relu(acc + bias) -> act[64][192]
    float* act = sB;
    {
        float4 bias = __ldg((const float4*)&g_b1f[j0]);
        #pragma unroll
        for (int r = 0; r < 4; r++) {
            float4 o;
            o.x = fmaxf(acc[r][0].x + bias.x, 0.f);
            o.y = fmaxf(acc[r][0].y + bias.y, 0.f);
            o.z = fmaxf(acc[r][1].x + bias.z, 0.f);
            o.w = fmaxf(acc[r][1].y + bias.w, 0.f);
            *(float4*)&act[(r0 + r) * 192 + j0] = o;
        }
    }
    __syncthreads();   // act complete

    // ---- Phase 2: warp-local 4x4 attention (warps 0..15, warp = sample)
    if (warp < 16) {
        const int s = warp, g = lane;
        float2 q2[4], k2[4], v2[4];
        #pragma unroll
        for (int l = 0; l < 4; l++) {
            const float* ar = act + (4 * s + l) * 192;
            q2[l] = *(const float2*)&ar[2 * g];
            k2[l] = *(const float2*)&ar[2 * g + 64];
            v2[l] = *(const float2*)&ar[2 * g + 128];
        }
        float sc[16];
        #pragma unroll
        for (int l = 0; l < 4; l++)
            #pragma unroll
            for (int m = 0; m < 4; m++)
                sc[l * 4 + m] = q2[l].x * k2[m].x + q2[l].y * k2[m].y;
        #pragma unroll
        for (int off = 16; off > 0; off >>= 1)
            #pragma unroll
            for (int i = 0; i < 16; i++)
                sc[i] += __shfl_xor_sync(0xffffffffu, sc[i], off);

        #pragma unroll
        for (int l = 0; l < 4; l++) {
            float s0 = sc[l*4+0], s1 = sc[l*4+1], s2 = sc[l*4+2], s3 = sc[l*4+3];
            float mx = fmaxf(fmaxf(s0, s1), fmaxf(s2, s3));
            float e0 = __expf(s0 - mx), e1 = __expf(s1 - mx);
            float e2 = __expf(s2 - mx), e3 = __expf(s3 - mx);
            float inv = 1.f / (e0 + e1 + e2 + e3);
            float ax = (e0*v2[0].x + e1*v2[1].x + e2*v2[2].x + e3*v2[3].x) * inv;
            float ay = (e0*v2[0].y + e1*v2[1].y + e2*v2[2].y + e3*v2[3].y) * inv;
            sATT[s * 260 + (2*g)   * 4 + l] = ax;
            sATT[s * 260 + (2*g+1) * 4 + l] = ay;
        }
    }
    __syncthreads();          // sATT complete; act dead -> yS region
    mbar_wait(MBAR + 24, 0);  // W4s resident

    // ---- Phase 3 (R8 alternation): GEMM2 warps<16; epilogue of prev chunk by
    //      warps 16..23; final epilogue by all 24.
    const float* W4s = sm;
    const int sI  = lane & 15;
    const int cgr = lane >> 4;

    auto compute_y = [&](int cc) {
        float* yb = sB + (cc & 1) * 8256;
        const int cb = cc * 128 + warp * 8 + cgr * 4;
        float2 y01[4], y23[4];
        #pragma unroll
        for (int cp = 0; cp < 4; cp++) {
            y01[cp] = make_float2(0.f, 0.f);
            y23[cp] = make_float2(0.f, 0.f);
        }
        const float* attn = sATT + sI * 260;
        const float* wp   = W4s + cb;
        float4 av = *(const float4*)&attn[0];
        float4 wv = *(const float4*)&wp[0];
        #pragma unroll 7
        for (int d = 0; d < 63; d++) {
            float4 avn = *(const float4*)&attn[(d + 1) * 4];
            float4 wvn = *(const float4*)&wp[(d + 1) * 512];
            float2 a01 = make_float2(av.x, av.y), a23 = make_float2(av.z, av.w);
            const float* wvp = &wv.x;
            #pragma unroll
            for (int cp = 0; cp < 4; cp++) {
                float2 wb = make_float2(wvp[cp], wvp[cp]);
                y01[cp] = ffma2(a01, wb, y01[cp]);
                y23[cp] = ffma2(a23, wb, y23[cp]);
            }
            av = avn; wv = wvn;
        }
        {
            float2 a01 = make_float2(av.x, av.y), a23 = make_float2(av.z, av.w);
            const float* wvp = &wv.x;
            #pragma unroll
            for (int cp = 0; cp < 4; cp++) {
                float2 wb = make_float2(wvp[cp], wvp[cp]);
                y01[cp] = ffma2(a01, wb, y01[cp]);
                y23[cp] = ffma2(a23, wb, y23[cp]);
            }
        }
        float4 cf = __ldg((const float4*)&g_c4f[cb]);
        const float* cfp = &cf.x;
        const int fb = (warp * 8 + cgr * 4) * 4;
        #pragma unroll
        for (int cp = 0; cp < 4; cp++) {
            *(float4*)&yb[sI * 516 + fb + cp * 4] =
                make_float4(y01[cp].x + cfp[cp], y01[cp].y + cfp[cp],
                            y23[cp].x + cfp[cp], y23[cp].y + cfp[cp]);
        }
    };
    auto epilogue = [&](int cc, int wfirst, int wcount) {
        const float* ys = sB + (cc & 1) * 8256;
        for (int u = warp - wfirst; u < 256; u += wcount) {
            const int s = u >> 4, i = u & 15;
            const int f = i * 32 + lane;
            float yv = ys[s * 516 + f];
            long b4i = ((long)(n0 + s) * 512 + cc * 128) * 4 + f;
            float4 v = __ldg(&xb[b4i]);
            v.x += yv; v.y += yv; v.z += yv; v.w += yv;
            ((float4*)out)[b4i] = v;
        }
    };

    if (warp < 16) compute_y(0);
    __syncthreads();
    #pragma unroll
    for (int cc = 1; cc < 4; cc++) {
        if (warp < 16) compute_y(cc);
        else           epilogue(cc - 1, 16, 8);
        __syncthreads();
    }
    epilogue(3, 0, 24);
}

extern "C" void kernel_launch(void* const* d_in, const int* in_sizes, int n_in,
                              void* d_out, int out_size)
{
    const float* x    = (const float*)d_in[0];
    const float* W123 = (const float*)d_in[1];
    const float* b123 = (const float*)d_in[2];
    const float* g123 = (const float*)d_in[3];
    const float* be123= (const float*)d_in[4];
    const float* m123 = (const float*)d_in[5];
    const float* v123 = (const float*)d_in[6];
    const float* W4   = (const float*)d_in[7];
    const float* b4   = (const float*)d_in[8];
    const float* g4   = (const float*)d_in[9];
    const float* be4  = (const float*)d_in[10];
    const float* m4   = (const float*)d_in[11];
    const float* v4   = (const float*)d_in[12];

    int N = in_sizes[0] / (512 * 16);   // 2048

    prep_kernel<<<129, 256>>>(W123, b123, g123, be123, m123, v123,
                              W4, b4, g4, be4, m4, v4);

    cudaFuncSetAttribute(fused_kernel, cudaFuncAttributeMaxDynamicSharedMemorySize,
                         SMF * 4);
    fused_kernel<<<N / 16, 768, SMF * 4>>>(x, (float*)d_out);
}

// round 14
// speedup vs baseline: 1.1283x; 1.0446x over previous
#include <cuda_runtime.h>
#include <string.h>
#include <stdint.h>

#define EPS 1e-5f

// ---------------- folded-weight scratch (device globals: allowed) ----------
__device__ __align__(16) float g_W1t[512 * 192];     // [c][j], BN1 scale folded
__device__ __align__(16) float g_b1f[192];           // BN1 folded bias
__device__ __align__(16) float g_W4c[4 * 64 * 128];  // [chunk][d][cl], BN2 folded
__device__ __align__(16) float g_c4f[512];           // BN2 folded bias

// ---------------- prep: fold BN into weights (tiled transposes) ------------
__global__ void prep_kernel(const float* __restrict__ W123, const float* __restrict__ b123,
                            const float* __restrict__ g123, const float* __restrict__ be123,
                            const float* __restrict__ m123, const float* __restrict__ v123,
                            const float* __restrict__ W4,   const float* __restrict__ b4,
                            const float* __restrict__ g4,   const float* __restrict__ be4,
                            const float* __restrict__ m4,   const float* __restrict__ v4)
{
    __shared__ float tile[32][33];
    const int b  = blockIdx.x;
    const int tx = threadIdx.x & 31;
    const int ty = threadIdx.x >> 5;          // 0..7

    if (b < 96) {
        // W1t[c][j] = W123[j][c] * s1[j]
        const int jt = b / 16, ct = b % 16;
        #pragma unroll
        for (int k = 0; k < 4; k++) {
            int jy = ty + k * 8;
            int j  = jt * 32 + jy, c = ct * 32 + tx;
            float s = g123[j] * rsqrtf(v123[j] + EPS);
            tile[jy][tx] = W123[j * 512 + c] * s;
        }
        __syncthreads();
        #pragma unroll
        for (int k = 0; k < 4; k++) {
            int cy = ty + k * 8;
            int c  = ct * 32 + cy, j = jt * 32 + tx;
            g_W1t[c * 192 + j] = tile[tx][cy];
        }
    } else if (b < 128) {
        // W4c[c>>7][d][c&127] = W4[c][d] * s4[c]
        const int bb = b - 96;
        const int dt = bb / 16, ct = bb % 16;
        #pragma unroll
        for (int k = 0; k < 4; k++) {
            int cy = ty + k * 8;
            int c  = ct * 32 + cy, d = dt * 32 + tx;
            float s = g4[c] * rsqrtf(v4[c] + EPS);
            tile[cy][tx] = W4[c * 64 + d] * s;
        }
        __syncthreads();
        #pragma unroll
        for (int k = 0; k < 4; k++) {
            int dy = ty + k * 8;
            int d  = dt * 32 + dy, c = ct * 32 + tx;
            g_W4c[(c >> 7) * 8192 + d * 128 + (c & 127)] = tile[tx][dy];
        }
    } else {
        int i = threadIdx.x;
        if (i < 192) {
            float s = g123[i] * rsqrtf(v123[i] + EPS);
            g_b1f[i] = (b123[i] - m123[i]) * s + be123[i];
        }
        for (int c = i; c < 512; c += 256) {
            float s = g4[c] * rsqrtf(v4[c] + EPS);
            g_c4f[c] = (b4[c] - m4[c]) * s + be4[c];
        }
    }
}

// ---------------- helpers ---------------------------------------------------
__device__ __forceinline__ float2 ffma2(float2 a, float2 b, float2 c) {
    unsigned long long au, bu, cu, du;
    memcpy(&au, &a, 8); memcpy(&bu, &b, 8); memcpy(&cu, &c, 8);
    asm("fma.rn.f32x2 %0, %1, %2, %3;" : "=l"(du) : "l"(au), "l"(bu), "l"(cu));
    float2 d; memcpy(&d, &du, 8); return d;
}
__device__ __forceinline__ uint32_t smem_u32(const void* p) {
    uint32_t a;
    asm("{ .reg .u64 t; cvta.to.shared.u64 t, %1; cvt.u32.u64 %0, t; }" : "=r"(a) : "l"(p));
    return a;
}
__device__ __forceinline__ void mbar_init(uint32_t a, uint32_t cnt) {
    asm volatile("mbarrier.init.shared.b64 [%0], %1;" :: "r"(a), "r"(cnt) : "memory");
}
__device__ __forceinline__ void mbar_expect_tx(uint32_t a, uint32_t bytes) {
    asm volatile("mbarrier.arrive.expect_tx.shared.b64 _, [%0], %1;" :: "r"(a), "r"(bytes) : "memory");
}
__device__ __forceinline__ void mbar_wait(uint32_t a, uint32_t parity) {
    asm volatile(
        "{\n\t.reg .pred P;\n\t"
        "WL%=:\n\t"
        "mbarrier.try_wait.parity.acquire.cta.shared::cta.b64 P, [%0], %1, 0x989680;\n\t"
        "@P bra WD%=;\n\t"
        "bra.uni WL%=;\n\t"
        "WD%=:\n\t}"
        :: "r"(a), "r"(parity) : "memory");
}
__device__ __forceinline__ void bulk_g2s(uint32_t dst_smem, const float* gsrc,
                                         uint32_t bytes, uint32_t mbar) {
    asm volatile(
        "cp.async.bulk.shared::cluster.global.mbarrier::complete_tx::bytes [%0], [%1], %2, [%3];"
        :: "r"(dst_smem), "l"(gsrc), "r"(bytes), "r"(mbar) : "memory");
}
#define NAMED_BAR(id) asm volatile("bar.sync %0, 384;" :: "r"(id) : "memory")
#define FENCE_ASYNC() asm volatile("fence.proxy.async.shared::cta;" ::: "memory")

// SMEM (floats):
//   [0, 34816)       A_T[512][68].  Post-GEMM1 reuse:
//                      partials [0,12288) ; act [18432,30720)
//                      W4 chunks 2x8192 [0,16384) ; yS buf1 [24576,32832)
//   [34816, 47104)   4 x 3072 GEMM1 weight stage bufs (2 per kh stream)
//                      post: yS buf0 [34816,43072)
//   [47104, 51264)   sATT 16 x 260
//   [51264, 51276)   6 mbarriers
#define SMF 51280

__global__ void __launch_bounds__(768, 1)
fused_kernel(const float* __restrict__ x, float* __restrict__ out)
{
    extern __shared__ float sm[];
    float* sAT  = sm;
    float* sRED = sm;                      // partials (post-GEMM1)
    float* act  = sm + 18432;
    float* sATT = sm + 47104;
    const uint32_t smb  = smem_u32(sm);
    const uint32_t smbW = smb + 34816u * 4u;
    const uint32_t MBAR = smb + 51264u * 4u;   // +8*i: i=0..3 weights, 4..5 W4

    const int t    = threadIdx.x;
    const int warp = t >> 5;               // 24 warps
    const int lane = t & 31;
    const int kh   = (warp >= 12);         // K-half
    const int wg   = kh ? warp - 12 : warp;   // 0..11 within group
    const int rt   = wg & 1;               // row tile (32 rows)
    const int ct   = wg >> 1;              // col tile (32 cols), 0..5
    const int n0   = blockIdx.x * 16;

    const int r0 = rt * 32 + (lane >> 3) * 8;   // 8 consecutive rows
    const int j0 = ct * 32 + (lane & 7) * 4;    // 4 consecutive cols

    if (t == 0) {
        #pragma unroll
        for (int i = 0; i < 6; i++) mbar_init(MBAR + 8u * i, 1);
    }
    __syncthreads();
    if (t == 0) {
        // initial weight stages: both streams, stages 0 and 1
        #pragma unroll
        for (int bi = 0; bi < 4; bi++) {
            int kk2 = (bi >> 1);            // stream (kh)
            int st  = (bi & 1);
            mbar_expect_tx(MBAR + 8u * bi, 12288);
            bulk_g2s(smbW + 12288u * bi, g_W1t + kk2 * 49152 + st * 3072,
                     12288, MBAR + 8u * bi);
        }
    }

    const float4* xb = (const float4*)x;

    // ---- Phase 0: gather xs into A_T[c][row], row=4*i+l (8-wf LDG pattern)
    {
        const int cl = lane >> 1;
        const int hs = lane & 1;
        for (int u = warp; u < 512; u += 24) {
            int i  = u >> 5, cb = u & 31;
            int c  = cb * 16 + cl;
            long f4 = ((long)(n0 + i) * 512 + c) * 4 + hs * 2;
            float4 v = __ldg(&xb[f4]);
            *(float2*)&sAT[c * 68 + 4 * i + 2 * hs] = make_float2(v.x, v.z);
        }
    }
    __syncthreads();

    // ---- Phase 1: GEMM1, thread tile 8r x 4c (row-pair packed), K-split x2.
    float2 acc[4][4];                      // [row-pair][col]
    #pragma unroll
    for (int rp = 0; rp < 4; rp++)
        #pragma unroll
        for (int c = 0; c < 4; c++) acc[rp][c] = make_float2(0.f, 0.f);

    #define FMA16(A0, A1, B)                                                    \
        do {                                                                    \
            float2 bd0 = make_float2((B).x, (B).x);                             \
            float2 bd1 = make_float2((B).y, (B).y);                             \
            float2 bd2 = make_float2((B).z, (B).z);                             \
            float2 bd3 = make_float2((B).w, (B).w);                             \
            float2 p0 = make_float2((A0).x, (A0).y);                            \
            float2 p1 = make_float2((A0).z, (A0).w);                            \
            float2 p2 = make_float2((A1).x, (A1).y);                            \
            float2 p3 = make_float2((A1).z, (A1).w);                            \
            acc[0][0] = ffma2(p0, bd0, acc[0][0]);                              \
            acc[0][1] = ffma2(p0, bd1, acc[0][1]);                              \
            acc[0][2] = ffma2(p0, bd2, acc[0][2]);                              \
            acc[0][3] = ffma2(p0, bd3, acc[0][3]);                              \
            acc[1][0] = ffma2(p1, bd0, acc[1][0]);                              \
            acc[1][1] = ffma2(p1, bd1, acc[1][1]);                              \
            acc[1][2] = ffma2(p1, bd2, acc[1][2]);                              \
            acc[1][3] = ffma2(p1, bd3, acc[1][3]);                              \
            acc[2][0] = ffma2(p2, bd0, acc[2][0]);                              \
            acc[2][1] = ffma2(p2, bd1, acc[2][1]);                              \
            acc[2][2] = ffma2(p2, bd2, acc[2][2]);                              \
            acc[2][3] = ffma2(p2, bd3, acc[2][3]);                              \
            acc[3][0] = ffma2(p3, bd0, acc[3][0]);                              \
            acc[3][1] = ffma2(p3, bd1, acc[3][1]);                              \
            acc[3][2] = ffma2(p3, bd2, acc[3][2]);                              \
            acc[3][3] = ffma2(p3, bd3, acc[3][3]);                              \
        } while (0)

    for (int st = 0; st < 16; st++) {
        const int bi = kh * 2 + (st & 1);
        mbar_wait(MBAR + 8u * bi, (st >> 1) & 1);

        const float* wbuf  = sm + 34816 + bi * 3072 + j0;
        const float* abase = sAT + (kh * 256 + st * 16) * 68 + r0;

        float4 a0 = *(const float4*)&abase[0];
        float4 a1 = *(const float4*)&abase[4];
        float4 b  = *(const float4*)&wbuf[0];
        #pragma unroll 15
        for (int kk = 0; kk < 15; kk++) {
            float4 a0n = *(const float4*)&abase[(kk + 1) * 68];
            float4 a1n = *(const float4*)&abase[(kk + 1) * 68 + 4];
            float4 bn  = *(const float4*)&wbuf[(kk + 1) * 192];
            FMA16(a0, a1, b);
            a0 = a0n; a1 = a1n; b = bn;
        }
        FMA16(a0, a1, b);

        NAMED_BAR(1 + kh);                 // group consumed this buffer

        if (st + 2 < 16 && t == kh * 384) {
            mbar_expect_tx(MBAR + 8u * bi, 12288);
            bulk_g2s(smbW + 12288u * bi, g_W1t + kh * 49152 + (st + 2) * 3072,
                     12288, MBAR + 8u * bi);
        }
    }
    __syncthreads();   // both groups done; A_T dead

    // ---- K-split reduction: kh1 dumps partials, kh0 adds + bias + relu -> act
    if (kh == 1) {
        float* rb = sRED + wg * 1024 + lane * 4;
        #pragma unroll
        for (int q = 0; q < 8; q++) {
            int rp = q >> 1, c0 = (q & 1) * 2;
            *(float4*)&rb[q * 128] = make_float4(acc[rp][c0].x, acc[rp][c0].y,
                                                 acc[rp][c0 + 1].x, acc[rp][c0 + 1].y);
        }
    }
    __syncthreads();
    if (kh == 0) {
        const float* rb = sRED + wg * 1024 + lane * 4;
        #pragma unroll
        for (int q = 0; q < 8; q++) {
            int rp = q >> 1, c0 = (q & 1) * 2;
            float4 p = *(const float4*)&rb[q * 128];
            acc[rp][c0].x     += p.x;  acc[rp][c0].y     += p.y;
            acc[rp][c0 + 1].x += p.z;  acc[rp][c0 + 1].y += p.w;
        }
        float4 bias = __ldg((const float4*)&g_b1f[j0]);
        #pragma unroll
        for (int rp = 0; rp < 4; rp++) {
            float4 ev, od;
            ev.x = fmaxf(acc[rp][0].x + bias.x, 0.f);
            ev.y = fmaxf(acc[rp][1].x + bias.y, 0.f);
            ev.z = fmaxf(acc[rp][2].x + bias.z, 0.f);
            ev.w = fmaxf(acc[rp][3].x + bias.w, 0.f);
            od.x = fmaxf(acc[rp][0].y + bias.x, 0.f);
            od.y = fmaxf(acc[rp][1].y + bias.y, 0.f);
            od.z = fmaxf(acc[rp][2].y + bias.z, 0.f);
            od.w = fmaxf(acc[rp][3].y + bias.w, 0.f);
            *(float4*)&act[(r0 + rp * 2 + 0) * 192 + j0] = ev;
            *(float4*)&act[(r0 + rp * 2 + 1) * 192 + j0] = od;
        }
    }
    __syncthreads();   // act complete; partials dead

    // ---- W4 chunks 0,1 into [0,16384) (async proxy over old generic writes)
    if (t == 0) {
        FENCE_ASYNC();
        mbar_expect_tx(MBAR + 32, 32768);
        bulk_g2s(smb,            g_W4c,        32768, MBAR + 32);
        mbar_expect_tx(MBAR + 40, 32768);
        bulk_g2s(smb + 32768u,   g_W4c + 8192, 32768, MBAR + 40);
    }

    // ---- Phase 2: warp-local 4x4 attention (warps 0..15, warp = sample)
    if (warp < 16) {
        const int s = warp, g = lane;
        float2 q2[4], k2[4], v2[4];
        #pragma unroll
        for (int l = 0; l < 4; l++) {
            const float* ar = act + (4 * s + l) * 192;
            q2[l] = *(const float2*)&ar[2 * g];
            k2[l] = *(const float2*)&ar[2 * g + 64];
            v2[l] = *(const float2*)&ar[2 * g + 128];
        }
        float sc[16];
        #pragma unroll
        for (int l = 0; l < 4; l++)
            #pragma unroll
            for (int m = 0; m < 4; m++)
                sc[l * 4 + m] = q2[l].x * k2[m].x + q2[l].y * k2[m].y;
        #pragma unroll
        for (int off = 16; off > 0; off >>= 1)
            #pragma unroll
            for (int i = 0; i < 16; i++)
                sc[i] += __shfl_xor_sync(0xffffffffu, sc[i], off);

        #pragma unroll
        for (int l = 0; l < 4; l++) {
            float s0 = sc[l*4+0], s1 = sc[l*4+1], s2 = sc[l*4+2], s3 = sc[l*4+3];
            float mx = fmaxf(fmaxf(s0, s1), fmaxf(s2, s3));
            float e0 = __expf(s0 - mx), e1 = __expf(s1 - mx);
            float e2 = __expf(s2 - mx), e3 = __expf(s3 - mx);
            float inv = 1.f / (e0 + e1 + e2 + e3);
            float ax = (e0*v2[0].x + e1*v2[1].x + e2*v2[2].x + e3*v2[3].x) * inv;
            float ay = (e0*v2[0].y + e1*v2[1].y + e2*v2[2].y + e3*v2[3].y) * inv;
            sATT[s * 260 + (2*g)   * 4 + l] = ax;
            sATT[s * 260 + (2*g+1) * 4 + l] = ay;
        }
    }
    __syncthreads();   // sATT complete; act dead

    // ---- Phase 3 (R8 alternation): GEMM2 warps<16; epilogue by warps 16..23;
    //      final epilogue by all. W4 chunks double-buffered at [0,16384).
    const int sI  = lane & 15;
    const int cgr = lane >> 4;

    auto ybuf = [&](int cc) -> float* {
        return (cc & 1) ? (sm + 24576) : (sm + 34816);
    };
    auto compute_y = [&](int cc) {
        float* yb = ybuf(cc);
        const int cb = cc * 128 + warp * 8 + cgr * 4;
        float2 y01[4], y23[4];
        #pragma unroll
        for (int cp = 0; cp < 4; cp++) {
            y01[cp] = make_float2(0.f, 0.f);
            y23[cp] = make_float2(0.f, 0.f);
        }
        const float* attn = sATT + sI * 260;
        const float* wp   = sm + (cc & 1) * 8192 + warp * 8 + cgr * 4;
        float4 av = *(const float4*)&attn[0];
        float4 wv = *(const float4*)&wp[0];
        #pragma unroll 7
        for (int d = 0; d < 63; d++) {
            float4 avn = *(const float4*)&attn[(d + 1) * 4];
            float4 wvn = *(const float4*)&wp[(d + 1) * 128];
            float2 a01 = make_float2(av.x, av.y), a23 = make_float2(av.z, av.w);
            const float* wvp = &wv.x;
            #pragma unroll
            for (int cp = 0; cp < 4; cp++) {
                float2 wb = make_float2(wvp[cp], wvp[cp]);
                y01[cp] = ffma2(a01, wb, y01[cp]);
                y23[cp] = ffma2(a23, wb, y23[cp]);
            }
            av = avn; wv = wvn;
        }
        {
            float2 a01 = make_float2(av.x, av.y), a23 = make_float2(av.z, av.w);
            const float* wvp = &wv.x;
            #pragma unroll
            for (int cp = 0; cp < 4; cp++) {
                float2 wb = make_float2(wvp[cp], wvp[cp]);
                y01[cp] = ffma2(a01, wb, y01[cp]);
                y23[cp] = ffma2(a23, wb, y23[cp]);
            }
        }
        float4 cf = __ldg((const float4*)&g_c4f[cb]);
        const float* cfp = &cf.x;
        const int fb = (warp * 8 + cgr * 4) * 4;
        #pragma unroll
        for (int cp = 0; cp < 4; cp++) {
            *(float4*)&yb[sI * 516 + fb + cp * 4] =
                make_float4(y01[cp].x + cfp[cp], y01[cp].y + cfp[cp],
                            y23[cp].x + cfp[cp], y23[cp].y + cfp[cp]);
        }
    };
    auto epilogue = [&](int cc, int wfirst, int wcount) {
        const float* ys = ybuf(cc);
        for (int u = warp - wfirst; u < 256; u += wcount) {
            const int s = u >> 4, i = u & 15;
            const int f = i * 32 + lane;
            float yv = ys[s * 516 + f];
            long b4i = ((long)(n0 + s) * 512 + cc * 128) * 4 + f;
            float4 v = __ldg(&xb[b4i]);
            v.x += yv; v.y += yv; v.z += yv; v.w += yv;
            ((float4*)out)[b4i] = v;
        }
    };

    mbar_wait(MBAR + 32, 0);               // chunk 0
    if (warp < 16) compute_y(0);
    __syncthreads();
    if (t == 0) {
        mbar_expect_tx(MBAR + 32, 32768);
        bulk_g2s(smb, g_W4c + 2 * 8192, 32768, MBAR + 32);     // chunk 2 -> buf0
    }
    #pragma unroll
    for (int cc = 1; cc < 4; cc++) {
        mbar_wait(MBAR + 32u + 8u * (cc & 1), (cc >> 1) & 1);
        if (warp < 16) compute_y(cc);
        else           epilogue(cc - 1, 16, 8);
        __syncthreads();
        if (cc == 1 && t == 0) {
            mbar_expect_tx(MBAR + 40, 32768);
            bulk_g2s(smb + 32768u, g_W4c + 3 * 8192, 32768, MBAR + 40);  // chunk 3
        }
    }
    epilogue(3, 0, 24);
}

extern "C" void kernel_launch(void* const* d_in, const int* in_sizes, int n_in,
                              void* d_out, int out_size)
{
    const float* x    = (const float*)d_in[0];
    const float* W123 = (const float*)d_in[1];
    const float* b123 = (const float*)d_in[2];
    const float* g123 = (const float*)d_in[3];
    const float* be123= (const float*)d_in[4];
    const float* m123 = (const float*)d_in[5];
    const float* v123 = (const float*)d_in[6];
    const float* W4   = (const float*)d_in[7];
    const float* b4   = (const float*)d_in[8];
    const float* g4   = (const float*)d_in[9];
    const float* be4  = (const float*)d_in[10];
    const float* m4   = (const float*)d_in[11];
    const float* v4   = (const float*)d_in[12];

    int N = in_sizes[0] / (512 * 16);   // 2048

    prep_kernel<<<129, 256>>>(W123, b123, g123, be123, m123, v123,
                              W4, b4, g4, be4, m4, v4);

    cudaFuncSetAttribute(fused_kernel, cudaFuncAttributeMaxDynamicSharedMemorySize,
                         SMF * 4);
    fused_kernel<<<N / 16, 768, SMF * 4>>>(x, (float*)d_out);
}